// round 16
// baseline (speedup 1.0000x reference)
#include <cuda_runtime.h>
#include <cuda_bf16.h>
#include <math.h>
#include <stdint.h>

// ---------------------------------------------------------------------------
// Problem constants
// ---------------------------------------------------------------------------
#define S_LEN   2048
#define HID     4096
#define Q_LORA  1536
#define KV_LORA 512
#define KV_IN   576
#define QKV_W   (Q_LORA + KV_IN)         // 2112
#define NH      16
#define QK_NOPE 128
#define QK_ROPE 64
#define Q_HEAD  192
#define V_DIM   128
#define QB_OUT  (NH * Q_HEAD)            // 3072
#define KVB_OUT (NH * (QK_NOPE + V_DIM)) // 4096
#define RMS_EPS 1e-6f
#define ROPE_BASE 10000.0f

typedef __nv_bfloat16 bf16;

// ---------------------------------------------------------------------------
// Static device scratch (split-2 [hi|lo]; GEMMs run 3 logical segment
// products: (Ahi,Bhi),(Ahi,Blo),(Alo,Bhi) per K-window)
// ---------------------------------------------------------------------------
__device__ float g_qkv_raw [S_LEN * QKV_W];
__device__ float g_qfull   [S_LEN * QB_OUT];
__device__ float g_kvexp   [S_LEN * KVB_OUT];

__device__ bf16 g_hidden2 [(size_t)S_LEN * 2 * HID];
__device__ bf16 g_wqkva2  [(size_t)QKV_W * 2 * HID];
__device__ bf16 g_qlat2   [(size_t)S_LEN * 2 * Q_LORA];
__device__ bf16 g_wqb2    [(size_t)QB_OUT * 2 * Q_LORA];
__device__ bf16 g_ckv2    [(size_t)S_LEN * 2 * KV_LORA];
__device__ bf16 g_wkvb2   [(size_t)KVB_OUT * 2 * KV_LORA];
__device__ bf16 g_Q2      [(size_t)NH * S_LEN * 2 * Q_HEAD];
__device__ bf16 g_K2      [(size_t)NH * S_LEN * 2 * Q_HEAD];
__device__ bf16 g_Vt2     [(size_t)NH * V_DIM * 2 * S_LEN];
__device__ bf16 g_attn2   [(size_t)S_LEN * 2 * (NH * V_DIM)];
__device__ bf16 g_wo2     [(size_t)HID * 2 * (NH * V_DIM)];

// ---------------------------------------------------------------------------
// helpers
// ---------------------------------------------------------------------------
__device__ __forceinline__ uint32_t smem_u32(const void* p) {
    return (uint32_t)__cvta_generic_to_shared(p);
}
__device__ __forceinline__ void ldsm_x4(uint32_t& r0, uint32_t& r1,
                                        uint32_t& r2, uint32_t& r3, uint32_t addr) {
    asm volatile("ldmatrix.sync.aligned.m8n8.x4.shared.b16 {%0,%1,%2,%3}, [%4];"
                 : "=r"(r0), "=r"(r1), "=r"(r2), "=r"(r3) : "r"(addr));
}
__device__ __forceinline__ void mma16816(float* c, const uint32_t* a, const uint32_t* b) {
    asm volatile("mma.sync.aligned.m16n8k16.row.col.f32.bf16.bf16.f32 "
                 "{%0,%1,%2,%3}, {%4,%5,%6,%7}, {%8,%9}, {%0,%1,%2,%3};"
                 : "+f"(c[0]), "+f"(c[1]), "+f"(c[2]), "+f"(c[3])
                 : "r"(a[0]), "r"(a[1]), "r"(a[2]), "r"(a[3]),
                   "r"(b[0]), "r"(b[1]));
}
__device__ __forceinline__ void cp16(uint32_t dst, const void* src, bool pred) {
    int sz = pred ? 16 : 0;
    asm volatile("cp.async.cg.shared.global [%0], [%1], 16, %2;"
                 :: "r"(dst), "l"(src), "r"(sz) : "memory");
}
__device__ __forceinline__ void cp_commit() {
    asm volatile("cp.async.commit_group;" ::: "memory");
}
__device__ __forceinline__ void cp_wait0() {
    asm volatile("cp.async.wait_group 0;" ::: "memory");
}
__device__ __forceinline__ void split2(float v, bf16& h, bf16& l) {
    h = __float2bfloat16(v);
    l = __float2bfloat16(v - __bfloat162float(h));
}

// ---------------------------------------------------------------------------
// Dense bf16 TN GEMM (R13/R15 proven, untouched)
// ---------------------------------------------------------------------------
#define GBM 128
#define GBK 32
#define SMPAD 40
#define TILE_B  (GBM * SMPAD * 2)   // 10240 B per tile
#define STAGE_B (4 * TILE_B)        // Ahi, Alo, Bhi, Blo
#define GEMM_SMEM (2 * STAGE_B)     // 81920 B

__global__ __launch_bounds__(256, 2)
void gemm_bf16_tn(const bf16* __restrict__ A, const bf16* __restrict__ B,
                  float* __restrict__ C, int M, int N, int Kb)
{
    const int bm = blockIdx.y * GBM;
    const int bn = blockIdx.x * GBM;

    extern __shared__ char smc[];
    const uint32_t sb = smem_u32(smc);

    const int tid  = threadIdx.x;
    const int lane = tid & 31;
    const int wid  = tid >> 5;
    const int wm   = (wid >> 2) * 64;
    const int wn   = (wid & 3) * 32;
    const int gid  = lane >> 2;
    const int tig  = lane & 3;

    const int lr = tid >> 2;            // 0..63
    const int lc = (tid & 3) * 8;       // 0,8,16,24 halves

    float acc[4][4][4];
#pragma unroll
    for (int a = 0; a < 4; a++)
#pragma unroll
        for (int b = 0; b < 4; b++)
#pragma unroll
            for (int c = 0; c < 4; c++) acc[a][b][c] = 0.f;

    const int rowlen = 2 * Kb;
    const int per_seg = Kb / GBK;

    const bool v0 = (bn + lr) < N;
    const bool v1 = (bn + lr + 64) < N;
    const uint32_t doff  = (uint32_t)((lr * SMPAD + lc) * 2);
    const uint32_t doff2 = (uint32_t)(((lr + 64) * SMPAD + lc) * 2);

    auto issue = [&](int w, int s) {
        const uint32_t st = sb + (uint32_t)s * STAGE_B;
        const int khi = w * GBK;
        const int klo = Kb + w * GBK;
        const bf16* Ap = A + (size_t)(bm + lr) * rowlen;
        const bf16* Bp = B + (size_t)(bn + lr) * rowlen;
        cp16(st + doff,               Ap + khi + lc,                        true);
        cp16(st + doff2,              Ap + (size_t)64 * rowlen + khi + lc,  true);
        cp16(st + TILE_B + doff,      Ap + klo + lc,                        true);
        cp16(st + TILE_B + doff2,     Ap + (size_t)64 * rowlen + klo + lc,  true);
        cp16(st + 2 * TILE_B + doff,  Bp + khi + lc,                        v0);
        cp16(st + 2 * TILE_B + doff2, Bp + (size_t)64 * rowlen + khi + lc,  v1);
        cp16(st + 3 * TILE_B + doff,  Bp + klo + lc,                        v0);
        cp16(st + 3 * TILE_B + doff2, Bp + (size_t)64 * rowlen + klo + lc,  v1);
    };

    const int a_row  = wm + (lane & 15);
    const int a_col  = (lane >> 4) * 8;
    const int b_row  = wn + (lane & 7);
    const int b_col4 = (lane >> 4) * 16 + ((lane >> 3) & 1) * 8;

    auto computeW = [&](uint32_t st) {
        uint32_t bqh[4][4], bql[4][4];
#pragma unroll
        for (int nt = 0; nt < 4; nt++) {
            const uint32_t bo = (uint32_t)(((b_row + nt * 8) * SMPAD + b_col4) * 2);
            ldsm_x4(bqh[nt][0], bqh[nt][1], bqh[nt][2], bqh[nt][3],
                    st + 2 * TILE_B + bo);
            ldsm_x4(bql[nt][0], bql[nt][1], bql[nt][2], bql[nt][3],
                    st + 3 * TILE_B + bo);
        }
#pragma unroll
        for (int ks = 0; ks < 2; ks++) {
            uint32_t af[4][4];
#pragma unroll
            for (int mt = 0; mt < 4; mt++) {
                const uint32_t ao =
                    (uint32_t)(((a_row + mt * 16) * SMPAD + ks * 16 + a_col) * 2);
                ldsm_x4(af[mt][0], af[mt][1], af[mt][2], af[mt][3], st + ao);  // Ahi
            }
#pragma unroll
            for (int mt = 0; mt < 4; mt++)
#pragma unroll
                for (int nt = 0; nt < 4; nt++)
                    mma16816(acc[mt][nt], af[mt], &bqh[nt][ks * 2]);   // hi*hi
#pragma unroll
            for (int mt = 0; mt < 4; mt++)
#pragma unroll
                for (int nt = 0; nt < 4; nt++)
                    mma16816(acc[mt][nt], af[mt], &bql[nt][ks * 2]);   // hi*lo
#pragma unroll
            for (int mt = 0; mt < 4; mt++) {
                const uint32_t ao =
                    (uint32_t)(((a_row + mt * 16) * SMPAD + ks * 16 + a_col) * 2);
                ldsm_x4(af[mt][0], af[mt][1], af[mt][2], af[mt][3],
                        st + TILE_B + ao);                              // Alo
            }
#pragma unroll
            for (int mt = 0; mt < 4; mt++)
#pragma unroll
                for (int nt = 0; nt < 4; nt++)
                    mma16816(acc[mt][nt], af[mt], &bqh[nt][ks * 2]);   // lo*hi
        }
    };

    issue(0, 0);
    cp_commit();
    for (int w = 0; w < per_seg; w++) {
        cp_wait0();
        __syncthreads();
        if (w + 1 < per_seg) { issue(w + 1, (w + 1) & 1); cp_commit(); }
        computeW(sb + (uint32_t)(w & 1) * STAGE_B);
    }

#pragma unroll
    for (int mt = 0; mt < 4; mt++) {
        const int row = bm + wm + mt * 16 + gid;
#pragma unroll
        for (int nt = 0; nt < 4; nt++) {
            const int col = bn + wn + nt * 8 + tig * 2;
            if (col < N) {
                *(float2*)&C[(size_t)row * N + col] =
                    make_float2(acc[mt][nt][0], acc[mt][nt][1]);
                *(float2*)&C[(size_t)(row + 8) * N + col] =
                    make_float2(acc[mt][nt][2], acc[mt][nt][3]);
            }
        }
    }
}

// ---------------------------------------------------------------------------
// Fused flash attention — Q & P resident, K/V streamed via cp.async
// co-resident hi/lo windows. Dead syncs removed (post-mask, post-PV).
// ---------------------------------------------------------------------------
#define QS_LDA  392
#define BUFB    (128 * SMPAD * 2)        // 10240 per tile
#define KV_STAGE (2 * BUFB)              // hi+lo tiles per stage
#define FL_QS   0
#define FL_BS   100352
#define FL_PS   141312
#define FL_WMAX 208896
#define FL_WSUM 210944
#define FL_RM   212992
#define FL_RL   213504
#define FL_RC   214016
#define FL_SMEM 214528
#define PS_LDA  264

__global__ __launch_bounds__(256)
void flash_attn()
{
    extern __shared__ char sm[];
    const uint32_t sb = smem_u32(sm);
    float* wmax  = (float*)(sm + FL_WMAX);
    float* wsum  = (float*)(sm + FL_WSUM);
    float* row_m = (float*)(sm + FL_RM);
    float* row_l = (float*)(sm + FL_RL);
    float* row_c = (float*)(sm + FL_RC);
    bf16*  Ps    = (bf16*)(sm + FL_PS);

    const int h    = blockIdx.y;
    const int tid  = threadIdx.x;
    const int lane = tid & 31;
    const int wid  = tid >> 5;
    const int wm   = (wid >> 2) * 64;
    const int wn   = (wid & 3) * 32;
    const int gid  = lane >> 2;
    const int tig  = lane & 3;
    const int lr   = tid >> 2;
    const int lc   = (tid & 3) * 8;
    const int wq   = wid & 3;

    const bf16* Qh = g_Q2 + (size_t)h * S_LEN * (2 * Q_HEAD);
    const bf16* Kh = g_K2 + (size_t)h * S_LEN * (2 * Q_HEAD);
    const bf16* Vh = g_Vt2 + (size_t)h * V_DIM * (2 * S_LEN);

    const int a_row  = wm + (lane & 15);
    const int a_col  = (lane >> 4) * 8;
    const int b_row  = wn + (lane & 7);
    const int b_col4 = (lane >> 4) * 16 + ((lane >> 3) & 1) * 8;

    const uint32_t doff  = (uint32_t)((lr * SMPAD + lc) * 2);
    const uint32_t doff2 = (uint32_t)(((lr + 64) * SMPAD + lc) * 2);

    for (int half = 0; half < 2; half++) {
        const int qb = half ? (15 - (int)blockIdx.x) : (int)blockIdx.x;
        const int q0 = qb * 128;

        if (tid < 128) { row_m[tid] = -1e30f; row_l[tid] = 0.f; }
        for (int idx = tid; idx < 128 * 48; idx += 256) {
            const int r = idx / 48, c = idx % 48;
            uint4 v = *(const uint4*)(Qh + (size_t)(q0 + r) * 384 + c * 8);
            *(uint4*)(sm + FL_QS + (uint32_t)((r * QS_LDA + c * 8) * 2)) = v;
        }
        float acc_o[4][4][4];
#pragma unroll
        for (int a = 0; a < 4; a++)
#pragma unroll
            for (int b = 0; b < 4; b++)
#pragma unroll
                for (int c = 0; c < 4; c++) acc_o[a][b][c] = 0.f;
        __syncthreads();

        for (int jb = 0; jb <= qb; jb++) {
            // ============== S = Q K^T : 6 windows, Q resident ==============
            float acc_s[4][4][4];
#pragma unroll
            for (int a = 0; a < 4; a++)
#pragma unroll
                for (int b = 0; b < 4; b++)
#pragma unroll
                    for (int c = 0; c < 4; c++) acc_s[a][b][c] = 0.f;

            auto issueK = [&](int w, int s) {
                const uint32_t st = sb + FL_BS + (uint32_t)s * KV_STAGE;
                const bf16* Kp = Kh + (size_t)(jb * 128 + lr) * 384 + lc;
                const bf16* Kp2 = Kp + (size_t)64 * 384;
                cp16(st + doff,         Kp  + w * 32,          true);
                cp16(st + doff2,        Kp2 + w * 32,          true);
                cp16(st + BUFB + doff,  Kp  + Q_HEAD + w * 32, true);
                cp16(st + BUFB + doff2, Kp2 + Q_HEAD + w * 32, true);
            };
            auto computeSW = [&](int w, uint32_t st) {
                uint32_t bqh[4][4], bql[4][4];
#pragma unroll
                for (int nt = 0; nt < 4; nt++) {
                    const uint32_t bo =
                        (uint32_t)(((b_row + nt * 8) * SMPAD + b_col4) * 2);
                    ldsm_x4(bqh[nt][0], bqh[nt][1], bqh[nt][2], bqh[nt][3], st + bo);
                    ldsm_x4(bql[nt][0], bql[nt][1], bql[nt][2], bql[nt][3],
                            st + BUFB + bo);
                }
#pragma unroll
                for (int ks = 0; ks < 2; ks++) {
                    uint32_t af[4][4];
#pragma unroll
                    for (int mt = 0; mt < 4; mt++) {
                        const uint32_t ao = (uint32_t)(((a_row + mt * 16) * QS_LDA +
                                             w * 32 + ks * 16 + a_col) * 2);
                        ldsm_x4(af[mt][0], af[mt][1], af[mt][2], af[mt][3],
                                sb + FL_QS + ao);                        // Qhi
                    }
#pragma unroll
                    for (int mt = 0; mt < 4; mt++)
#pragma unroll
                        for (int nt = 0; nt < 4; nt++)
                            mma16816(acc_s[mt][nt], af[mt], &bqh[nt][ks * 2]);
#pragma unroll
                    for (int mt = 0; mt < 4; mt++)
#pragma unroll
                        for (int nt = 0; nt < 4; nt++)
                            mma16816(acc_s[mt][nt], af[mt], &bql[nt][ks * 2]);
#pragma unroll
                    for (int mt = 0; mt < 4; mt++) {
                        const uint32_t ao = (uint32_t)(((a_row + mt * 16) * QS_LDA +
                                             Q_HEAD + w * 32 + ks * 16 + a_col) * 2);
                        ldsm_x4(af[mt][0], af[mt][1], af[mt][2], af[mt][3],
                                sb + FL_QS + ao);                        // Qlo
                    }
#pragma unroll
                    for (int mt = 0; mt < 4; mt++)
#pragma unroll
                        for (int nt = 0; nt < 4; nt++)
                            mma16816(acc_s[mt][nt], af[mt], &bqh[nt][ks * 2]);
                }
            };

            issueK(0, 0);
            cp_commit();
            for (int w = 0; w < 6; w++) {
                cp_wait0();
                __syncthreads();
                if (w + 1 < 6) { issueK(w + 1, (w + 1) & 1); cp_commit(); }
                computeSW(w, sb + FL_BS + (uint32_t)(w & 1) * KV_STAGE);
            }

            // mask (diagonal block) — register-only, no barrier needed
            if (jb == qb) {
#pragma unroll
                for (int mt = 0; mt < 4; mt++) {
                    const int m0 = wm + mt * 16 + gid;
#pragma unroll
                    for (int nt = 0; nt < 4; nt++) {
                        const int n0 = wn + nt * 8 + tig * 2;
                        if (n0     > m0    ) acc_s[mt][nt][0] = -1e30f;
                        if (n0 + 1 > m0    ) acc_s[mt][nt][1] = -1e30f;
                        if (n0     > m0 + 8) acc_s[mt][nt][2] = -1e30f;
                        if (n0 + 1 > m0 + 8) acc_s[mt][nt][3] = -1e30f;
                    }
                }
            }

            // row max (warp-local, cross-warp via smem)
            float rmx[4][2];
#pragma unroll
            for (int mt = 0; mt < 4; mt++) {
                float m0 = -1e30f, m1 = -1e30f;
#pragma unroll
                for (int nt = 0; nt < 4; nt++) {
                    m0 = fmaxf(m0, fmaxf(acc_s[mt][nt][0], acc_s[mt][nt][1]));
                    m1 = fmaxf(m1, fmaxf(acc_s[mt][nt][2], acc_s[mt][nt][3]));
                }
                rmx[mt][0] = m0; rmx[mt][1] = m1;
            }
#pragma unroll
            for (int o = 1; o < 4; o <<= 1)
#pragma unroll
                for (int mt = 0; mt < 4; mt++) {
                    rmx[mt][0] = fmaxf(rmx[mt][0], __shfl_xor_sync(0xffffffffu, rmx[mt][0], o));
                    rmx[mt][1] = fmaxf(rmx[mt][1], __shfl_xor_sync(0xffffffffu, rmx[mt][1], o));
                }
            if (tig == 0) {
#pragma unroll
                for (int mt = 0; mt < 4; mt++) {
                    wmax[wq * 128 + wm + mt * 16 + gid]     = rmx[mt][0];
                    wmax[wq * 128 + wm + mt * 16 + gid + 8] = rmx[mt][1];
                }
            }
            __syncthreads();

            // P = exp(S-new_m), write Ps (hi|lo), partial sums
            float psum[4][2];
#pragma unroll
            for (int mt = 0; mt < 4; mt++) {
#pragma unroll
                for (int rr = 0; rr < 2; rr++) {
                    const int r = wm + mt * 16 + gid + rr * 8;
                    float bmx = fmaxf(fmaxf(wmax[r], wmax[128 + r]),
                                      fmaxf(wmax[256 + r], wmax[384 + r]));
                    const float newm = fmaxf(row_m[r], bmx);
                    float s = 0.f;
#pragma unroll
                    for (int nt = 0; nt < 4; nt++) {
                        const int n0 = wn + nt * 8 + tig * 2;
                        float p0 = __expf(acc_s[mt][nt][rr * 2 + 0] - newm);
                        float p1 = __expf(acc_s[mt][nt][rr * 2 + 1] - newm);
                        s += p0 + p1;
                        bf16 h0, l0, h1, l1;
                        split2(p0, h0, l0); split2(p1, h1, l1);
                        __nv_bfloat162 hp, lp;
                        hp.x = h0; hp.y = h1; lp.x = l0; lp.y = l1;
                        *(__nv_bfloat162*)&Ps[r * PS_LDA + n0]       = hp;
                        *(__nv_bfloat162*)&Ps[r * PS_LDA + 128 + n0] = lp;
                    }
                    psum[mt][rr] = s;
                }
            }
#pragma unroll
            for (int o = 1; o < 4; o <<= 1)
#pragma unroll
                for (int mt = 0; mt < 4; mt++) {
                    psum[mt][0] += __shfl_xor_sync(0xffffffffu, psum[mt][0], o);
                    psum[mt][1] += __shfl_xor_sync(0xffffffffu, psum[mt][1], o);
                }
            if (tig == 0) {
#pragma unroll
                for (int mt = 0; mt < 4; mt++) {
                    wsum[wq * 128 + wm + mt * 16 + gid]     = psum[mt][0];
                    wsum[wq * 128 + wm + mt * 16 + gid + 8] = psum[mt][1];
                }
            }
            __syncthreads();

            // per-row state update
            if (tid < 128) {
                const int r = tid;
                float bmx = fmaxf(fmaxf(wmax[r], wmax[128 + r]),
                                  fmaxf(wmax[256 + r], wmax[384 + r]));
                const float old  = row_m[r];
                const float newm = fmaxf(old, bmx);
                const float corr = __expf(old - newm);
                const float bs = wsum[r] + wsum[128 + r] + wsum[256 + r] + wsum[384 + r];
                row_l[r] = row_l[r] * corr + bs;
                row_m[r] = newm;
                row_c[r] = corr;
            }
            __syncthreads();

#pragma unroll
            for (int mt = 0; mt < 4; mt++) {
                const float c0 = row_c[wm + mt * 16 + gid];
                const float c1 = row_c[wm + mt * 16 + gid + 8];
#pragma unroll
                for (int nt = 0; nt < 4; nt++) {
                    acc_o[mt][nt][0] *= c0; acc_o[mt][nt][1] *= c0;
                    acc_o[mt][nt][2] *= c1; acc_o[mt][nt][3] *= c1;
                }
            }

            // ============== O += P V : 4 windows, P resident ===============
            auto issueV = [&](int w, int s) {
                const uint32_t st = sb + FL_BS + (uint32_t)s * KV_STAGE;
                const bf16* Vp = Vh + (size_t)lr * (2 * S_LEN) + jb * 128 + lc;
                const bf16* Vp2 = Vp + (size_t)64 * (2 * S_LEN);
                cp16(st + doff,         Vp  + w * 32,         true);
                cp16(st + doff2,        Vp2 + w * 32,         true);
                cp16(st + BUFB + doff,  Vp  + S_LEN + w * 32, true);
                cp16(st + BUFB + doff2, Vp2 + S_LEN + w * 32, true);
            };
            auto computePVW = [&](int w, uint32_t st) {
                uint32_t bqh[4][4], bql[4][4];
#pragma unroll
                for (int nt = 0; nt < 4; nt++) {
                    const uint32_t bo =
                        (uint32_t)(((b_row + nt * 8) * SMPAD + b_col4) * 2);
                    ldsm_x4(bqh[nt][0], bqh[nt][1], bqh[nt][2], bqh[nt][3], st + bo);
                    ldsm_x4(bql[nt][0], bql[nt][1], bql[nt][2], bql[nt][3],
                            st + BUFB + bo);
                }
#pragma unroll
                for (int ks = 0; ks < 2; ks++) {
                    uint32_t af[4][4];
#pragma unroll
                    for (int mt = 0; mt < 4; mt++) {
                        const uint32_t ao = (uint32_t)(((a_row + mt * 16) * PS_LDA +
                                             w * 32 + ks * 16 + a_col) * 2);
                        ldsm_x4(af[mt][0], af[mt][1], af[mt][2], af[mt][3],
                                sb + FL_PS + ao);                        // Phi
                    }
#pragma unroll
                    for (int mt = 0; mt < 4; mt++)
#pragma unroll
                        for (int nt = 0; nt < 4; nt++)
                            mma16816(acc_o[mt][nt], af[mt], &bqh[nt][ks * 2]);
#pragma unroll
                    for (int mt = 0; mt < 4; mt++)
#pragma unroll
                        for (int nt = 0; nt < 4; nt++)
                            mma16816(acc_o[mt][nt], af[mt], &bql[nt][ks * 2]);
#pragma unroll
                    for (int mt = 0; mt < 4; mt++) {
                        const uint32_t ao = (uint32_t)(((a_row + mt * 16) * PS_LDA +
                                             128 + w * 32 + ks * 16 + a_col) * 2);
                        ldsm_x4(af[mt][0], af[mt][1], af[mt][2], af[mt][3],
                                sb + FL_PS + ao);                        // Plo
                    }
#pragma unroll
                    for (int mt = 0; mt < 4; mt++)
#pragma unroll
                        for (int nt = 0; nt < 4; nt++)
                            mma16816(acc_o[mt][nt], af[mt], &bqh[nt][ks * 2]);
                }
            };

            issueV(0, 0);
            cp_commit();
            for (int w = 0; w < 4; w++) {
                cp_wait0();
                __syncthreads();
                if (w + 1 < 4) { issueV(w + 1, (w + 1) & 1); cp_commit(); }
                computePVW(w, sb + FL_BS + (uint32_t)(w & 1) * KV_STAGE);
            }
            // no trailing sync: next iteration's first stage-0 write is
            // ordered behind the w-loop head barrier; Ps writes are behind
            // two more barriers.
        }

        // epilogue: O / l -> attn2 (split-2)
#pragma unroll
        for (int mt = 0; mt < 4; mt++) {
            const int r0 = wm + mt * 16 + gid;
            const int r1 = r0 + 8;
            const float inv0 = 1.f / row_l[r0];
            const float inv1 = 1.f / row_l[r1];
            bf16* d0 = g_attn2 + (size_t)(q0 + r0) * (2 * NH * V_DIM);
            bf16* d1 = g_attn2 + (size_t)(q0 + r1) * (2 * NH * V_DIM);
#pragma unroll
            for (int nt = 0; nt < 4; nt++) {
                const int c = h * V_DIM + wn + nt * 8 + tig * 2;
                bf16 h0, l0, h1, l1;
                split2(acc_o[mt][nt][0] * inv0, h0, l0);
                split2(acc_o[mt][nt][1] * inv0, h1, l1);
                __nv_bfloat162 hp, lp;
                hp.x = h0; hp.y = h1; lp.x = l0; lp.y = l1;
                *(__nv_bfloat162*)&d0[c]              = hp;
                *(__nv_bfloat162*)&d0[NH * V_DIM + c] = lp;
                split2(acc_o[mt][nt][2] * inv1, h0, l0);
                split2(acc_o[mt][nt][3] * inv1, h1, l1);
                hp.x = h0; hp.y = h1; lp.x = l0; lp.y = l1;
                *(__nv_bfloat162*)&d1[c]              = hp;
                *(__nv_bfloat162*)&d1[NH * V_DIM + c] = lp;
            }
        }
        __syncthreads();   // row state / Qs reuse by next half
    }
}

// ---------------------------------------------------------------------------
// One merged split-2 kernel for all 6 input/weight splits
// ---------------------------------------------------------------------------
struct SplitArgs {
    const float* x0; bf16* y0;
    const float* x1; bf16* y1;
    const float* x2; bf16* y2;
    const float* x3; bf16* y3;
    const float* x4; bf16* y4;
    const float* x5; bf16* y5;
};

__global__ __launch_bounds__(256)
void split2_all(SplitArgs args)
{
    int b = blockIdx.x;
    const float* x; bf16* y; int C, row;
    if      (b < 2048)  { x = args.x0; y = args.y0; C = 4096; row = b; }
    else if (b < 3584)  { x = args.x1; y = args.y1; C = 4096; row = b - 2048; }
    else if (b < 4160)  { x = args.x2; y = args.y2; C = 4096; row = b - 3584; }
    else if (b < 7232)  { x = args.x3; y = args.y3; C = 1536; row = b - 4160; }
    else if (b < 11328) { x = args.x4; y = args.y4; C = 512;  row = b - 7232; }
    else                { x = args.x5; y = args.y5; C = 2048; row = b - 11328; }

    const float* xr = x + (size_t)row * C;
    bf16* yr = y + (size_t)row * 2 * C;
    for (int j = threadIdx.x * 4; j < C; j += 256 * 4) {
        float4 v = *(const float4*)&xr[j];
        bf16 h0, l0, h1, l1, h2, l2, h3, l3;
        split2(v.x, h0, l0); split2(v.y, h1, l1);
        split2(v.z, h2, l2); split2(v.w, h3, l3);
        __nv_bfloat162 hh01, hh23, ll01, ll23;
        hh01.x = h0; hh01.y = h1; hh23.x = h2; hh23.y = h3;
        ll01.x = l0; ll01.y = l1; ll23.x = l2; ll23.y = l3;
        *(__nv_bfloat162*)&yr[j]         = hh01;
        *(__nv_bfloat162*)&yr[j + 2]     = hh23;
        *(__nv_bfloat162*)&yr[C + j]     = ll01;
        *(__nv_bfloat162*)&yr[C + j + 2] = ll23;
    }
}

// ---------------------------------------------------------------------------
// Merged RMSNorm (q rows then kv rows) fused with split-2 output
// ---------------------------------------------------------------------------
__global__ __launch_bounds__(256)
void rmsnorm_split_all(const float* __restrict__ qkv,
                       const float* __restrict__ qw,
                       const float* __restrict__ kw,
                       bf16* __restrict__ yq, bf16* __restrict__ yk)
{
    const int b = blockIdx.x;
    const float* xr; const float* w; bf16* yr; int len;
    if (b < S_LEN) {
        xr = qkv + (size_t)b * QKV_W;           w = qw;
        yr = yq + (size_t)b * 2 * Q_LORA;       len = Q_LORA;
    } else {
        const int r = b - S_LEN;
        xr = qkv + (size_t)r * QKV_W + Q_LORA;  w = kw;
        yr = yk + (size_t)r * 2 * KV_LORA;      len = KV_LORA;
    }

    float ss = 0.f;
    for (int j = threadIdx.x; j < len; j += 256) { float v = xr[j]; ss += v * v; }
    __shared__ float red[256];
    red[threadIdx.x] = ss;
    __syncthreads();
    for (int s = 128; s > 0; s >>= 1) {
        if (threadIdx.x < s) red[threadIdx.x] += red[threadIdx.x + s];
        __syncthreads();
    }
    const float inv = rsqrtf(red[0] / (float)len + RMS_EPS);
    for (int j = threadIdx.x; j < len; j += 256) {
        bf16 h, l;
        split2(w[j] * xr[j] * inv, h, l);
        yr[j] = h; yr[len + j] = l;
    }
}

// ---------------------------------------------------------------------------
// RoPE + merged Q/K assemble (2 sequence positions per block), V transpose
// ---------------------------------------------------------------------------
__device__ __forceinline__ void rope_cs(int pos, int jj, float& c, float& s)
{
    int i = jj & 31;
    float inv = __expf(-((float)(2 * i) / (float)QK_ROPE) * logf(ROPE_BASE));
    float ang = (float)pos * inv;
    c = cosf(ang);
    s = sinf(ang);
}

__global__ __launch_bounds__(768)
void assemble_qk(float scale)
{
    const int h = blockIdx.y;
    const int s = blockIdx.x * 2 + (threadIdx.x / 384);
    const int t = threadIdx.x % 384;
    if (t < Q_HEAD) {
        const int j = t;
        const float* src = g_qfull + (size_t)s * QB_OUT + h * Q_HEAD;
        float v = src[j];
        if (j >= QK_NOPE) {
            int jj = j - QK_NOPE;
            float c, sn;
            rope_cs(s, jj, c, sn);
            float other = (jj < 32) ? -src[QK_NOPE + jj + 32] : src[QK_NOPE + jj - 32];
            v = v * c + other * sn;
        }
        v *= scale;
        bf16 hh, ll;
        split2(v, hh, ll);
        bf16* dst = g_Q2 + ((size_t)h * S_LEN + s) * 2 * Q_HEAD;
        dst[j] = hh; dst[Q_HEAD + j] = ll;
    } else {
        const int j = t - Q_HEAD;
        float v;
        if (j < QK_NOPE) {
            v = g_kvexp[(size_t)s * KVB_OUT + h * (QK_NOPE + V_DIM) + j];
        } else {
            int jj = j - QK_NOPE;
            const float* pe = g_qkv_raw + (size_t)s * QKV_W + Q_LORA + KV_LORA;
            float c, sn;
            rope_cs(s, jj, c, sn);
            float other = (jj < 32) ? -pe[jj + 32] : pe[jj - 32];
            v = pe[jj] * c + other * sn;
        }
        bf16 hh, ll;
        split2(v, hh, ll);
        bf16* dst = g_K2 + ((size_t)h * S_LEN + s) * 2 * Q_HEAD;
        dst[j] = hh; dst[Q_HEAD + j] = ll;
    }
}

__global__ void assemble_vt()
{
    __shared__ float sm[32][33];
    const int h = blockIdx.z;
    const int s0 = blockIdx.x * 32, d0 = blockIdx.y * 32;
    const int tx = threadIdx.x, ty = threadIdx.y;
    sm[ty][tx] = g_kvexp[(size_t)(s0 + ty) * KVB_OUT +
                         h * (QK_NOPE + V_DIM) + QK_NOPE + d0 + tx];
    __syncthreads();
    const int d = d0 + ty, s = s0 + tx;
    bf16 hh, ll;
    split2(sm[tx][ty], hh, ll);
    bf16* dst = g_Vt2 + ((size_t)h * V_DIM + d) * 2 * S_LEN;
    dst[s] = hh; dst[S_LEN + s] = ll;
}

// ---------------------------------------------------------------------------
// Host launch
// ---------------------------------------------------------------------------
extern "C" void kernel_launch(void* const* d_in, const int* in_sizes, int n_in,
                              void* d_out, int out_size)
{
    (void)in_sizes; (void)n_in; (void)out_size;
    const float* hidden = (const float*)d_in[0];
    const float* wq_a   = (const float*)d_in[2];
    const float* qnw    = (const float*)d_in[3];
    const float* wq_b   = (const float*)d_in[4];
    const float* wkv_a  = (const float*)d_in[5];
    const float* kvnw   = (const float*)d_in[6];
    const float* wkv_b  = (const float*)d_in[7];
    const float* wo     = (const float*)d_in[8];
    float* out = (float*)d_out;

    float *qkv_raw, *qfull, *kvexp;
    bf16 *hidden2, *wqkva2, *qlat2, *wqb2, *ckv2, *wkvb2, *attn2, *wo2;
    cudaGetSymbolAddress((void**)&qkv_raw, g_qkv_raw);
    cudaGetSymbolAddress((void**)&qfull,   g_qfull);
    cudaGetSymbolAddress((void**)&kvexp,   g_kvexp);
    cudaGetSymbolAddress((void**)&hidden2, g_hidden2);
    cudaGetSymbolAddress((void**)&wqkva2,  g_wqkva2);
    cudaGetSymbolAddress((void**)&qlat2,   g_qlat2);
    cudaGetSymbolAddress((void**)&wqb2,    g_wqb2);
    cudaGetSymbolAddress((void**)&ckv2,    g_ckv2);
    cudaGetSymbolAddress((void**)&wkvb2,   g_wkvb2);
    cudaGetSymbolAddress((void**)&attn2,   g_attn2);
    cudaGetSymbolAddress((void**)&wo2,     g_wo2);

    const float softmax_scale = rsqrtf((float)Q_HEAD);
    dim3 blk(256);

    cudaFuncSetAttribute(flash_attn, cudaFuncAttributeMaxDynamicSharedMemorySize,
                         FL_SMEM);
    cudaFuncSetAttribute(gemm_bf16_tn, cudaFuncAttributeMaxDynamicSharedMemorySize,
                         GEMM_SMEM);

    SplitArgs sa;
    sa.x0 = hidden; sa.y0 = hidden2;
    sa.x1 = wq_a;   sa.y1 = wqkva2;
    sa.x2 = wkv_a;  sa.y2 = wqkva2 + (size_t)Q_LORA * 2 * HID;
    sa.x3 = wq_b;   sa.y3 = wqb2;
    sa.x4 = wkv_b;  sa.y4 = wkvb2;
    sa.x5 = wo;     sa.y5 = wo2;
    split2_all<<<15424, 256>>>(sa);

    // 1+2 fused: [q_lat_raw | kv] = hidden @ [wq_a | wkv_a]^T
    gemm_bf16_tn<<<dim3((QKV_W + 127) / 128, S_LEN / 128, 1), blk, GEMM_SMEM>>>(
        hidden2, wqkva2, qkv_raw, S_LEN, QKV_W, HID);
    // merged RMSNorms
    rmsnorm_split_all<<<2 * S_LEN, 256>>>(qkv_raw, qnw, kvnw, qlat2, ckv2);
    // q = q_lat @ wq_b^T
    gemm_bf16_tn<<<dim3(QB_OUT / 128, S_LEN / 128, 1), blk, GEMM_SMEM>>>(
        qlat2, wqb2, qfull, S_LEN, QB_OUT, Q_LORA);
    // kv_exp = ckv @ wkv_b^T
    gemm_bf16_tn<<<dim3(KVB_OUT / 128, S_LEN / 128, 1), blk, GEMM_SMEM>>>(
        ckv2, wkvb2, kvexp, S_LEN, KVB_OUT, KV_LORA);

    // assemble attention operands
    assemble_qk<<<dim3(S_LEN / 2, NH), 768>>>(softmax_scale);
    assemble_vt<<<dim3(S_LEN / 32, V_DIM / 32, NH), dim3(32, 32)>>>();

    // fused flash attention (Q/P resident, cp.async K/V windows)
    flash_attn<<<dim3(8, NH), blk, FL_SMEM>>>();

    // output projection
    gemm_bf16_tn<<<dim3(HID / 128, S_LEN / 128, 1), blk, GEMM_SMEM>>>(
        attn2, wo2, out, S_LEN, HID, NH * V_DIM);
}

// round 17
// speedup vs baseline: 1.0132x; 1.0132x over previous
#include <cuda_runtime.h>
#include <cuda_bf16.h>
#include <math.h>
#include <stdint.h>

// ---------------------------------------------------------------------------
// Problem constants
// ---------------------------------------------------------------------------
#define S_LEN   2048
#define HID     4096
#define Q_LORA  1536
#define KV_LORA 512
#define KV_IN   576
#define QKV_W   (Q_LORA + KV_IN)         // 2112
#define NH      16
#define QK_NOPE 128
#define QK_ROPE 64
#define Q_HEAD  192
#define V_DIM   128
#define QB_OUT  (NH * Q_HEAD)            // 3072
#define KVB_OUT (NH * (QK_NOPE + V_DIM)) // 4096
#define RMS_EPS 1e-6f
#define ROPE_BASE 10000.0f

typedef __nv_bfloat16 bf16;

// ---------------------------------------------------------------------------
// Static device scratch (split-2 [hi|lo]; GEMMs run 3 logical segment
// products: (Ahi,Bhi),(Ahi,Blo),(Alo,Bhi) per K-window)
// ---------------------------------------------------------------------------
__device__ float g_qkv_raw [S_LEN * QKV_W];
__device__ float g_qfull   [S_LEN * QB_OUT];
__device__ float g_kvexp   [S_LEN * KVB_OUT];

__device__ bf16 g_hidden2 [(size_t)S_LEN * 2 * HID];
__device__ bf16 g_wqkva2  [(size_t)QKV_W * 2 * HID];
__device__ bf16 g_qlat2   [(size_t)S_LEN * 2 * Q_LORA];
__device__ bf16 g_wqb2    [(size_t)QB_OUT * 2 * Q_LORA];
__device__ bf16 g_ckv2    [(size_t)S_LEN * 2 * KV_LORA];
__device__ bf16 g_wkvb2   [(size_t)KVB_OUT * 2 * KV_LORA];
__device__ bf16 g_Q2      [(size_t)NH * S_LEN * 2 * Q_HEAD];
__device__ bf16 g_K2      [(size_t)NH * S_LEN * 2 * Q_HEAD];
__device__ bf16 g_Vt2     [(size_t)NH * V_DIM * 2 * S_LEN];
__device__ bf16 g_attn2   [(size_t)S_LEN * 2 * (NH * V_DIM)];
__device__ bf16 g_wo2     [(size_t)HID * 2 * (NH * V_DIM)];

// ---------------------------------------------------------------------------
// helpers
// ---------------------------------------------------------------------------
__device__ __forceinline__ uint32_t smem_u32(const void* p) {
    return (uint32_t)__cvta_generic_to_shared(p);
}
__device__ __forceinline__ void ldsm_x4(uint32_t& r0, uint32_t& r1,
                                        uint32_t& r2, uint32_t& r3, uint32_t addr) {
    asm volatile("ldmatrix.sync.aligned.m8n8.x4.shared.b16 {%0,%1,%2,%3}, [%4];"
                 : "=r"(r0), "=r"(r1), "=r"(r2), "=r"(r3) : "r"(addr));
}
__device__ __forceinline__ void mma16816(float* c, const uint32_t* a, const uint32_t* b) {
    asm volatile("mma.sync.aligned.m16n8k16.row.col.f32.bf16.bf16.f32 "
                 "{%0,%1,%2,%3}, {%4,%5,%6,%7}, {%8,%9}, {%0,%1,%2,%3};"
                 : "+f"(c[0]), "+f"(c[1]), "+f"(c[2]), "+f"(c[3])
                 : "r"(a[0]), "r"(a[1]), "r"(a[2]), "r"(a[3]),
                   "r"(b[0]), "r"(b[1]));
}
__device__ __forceinline__ void cp16(uint32_t dst, const void* src, bool pred) {
    int sz = pred ? 16 : 0;
    asm volatile("cp.async.cg.shared.global [%0], [%1], 16, %2;"
                 :: "r"(dst), "l"(src), "r"(sz) : "memory");
}
__device__ __forceinline__ void cp_commit() {
    asm volatile("cp.async.commit_group;" ::: "memory");
}
__device__ __forceinline__ void cp_wait0() {
    asm volatile("cp.async.wait_group 0;" ::: "memory");
}
__device__ __forceinline__ void split2(float v, bf16& h, bf16& l) {
    h = __float2bfloat16(v);
    l = __float2bfloat16(v - __bfloat162float(h));
}

// ---------------------------------------------------------------------------
// Dense bf16 TN GEMM (R13/R15 proven, untouched)
// ---------------------------------------------------------------------------
#define GBM 128
#define GBK 32
#define SMPAD 40
#define TILE_B  (GBM * SMPAD * 2)   // 10240 B per tile
#define STAGE_B (4 * TILE_B)        // Ahi, Alo, Bhi, Blo
#define GEMM_SMEM (2 * STAGE_B)     // 81920 B

__global__ __launch_bounds__(256, 2)
void gemm_bf16_tn(const bf16* __restrict__ A, const bf16* __restrict__ B,
                  float* __restrict__ C, int M, int N, int Kb)
{
    const int bm = blockIdx.y * GBM;
    const int bn = blockIdx.x * GBM;

    extern __shared__ char smc[];
    const uint32_t sb = smem_u32(smc);

    const int tid  = threadIdx.x;
    const int lane = tid & 31;
    const int wid  = tid >> 5;
    const int wm   = (wid >> 2) * 64;
    const int wn   = (wid & 3) * 32;
    const int gid  = lane >> 2;
    const int tig  = lane & 3;

    const int lr = tid >> 2;            // 0..63
    const int lc = (tid & 3) * 8;       // 0,8,16,24 halves

    float acc[4][4][4];
#pragma unroll
    for (int a = 0; a < 4; a++)
#pragma unroll
        for (int b = 0; b < 4; b++)
#pragma unroll
            for (int c = 0; c < 4; c++) acc[a][b][c] = 0.f;

    const int rowlen = 2 * Kb;
    const int per_seg = Kb / GBK;

    const bool v0 = (bn + lr) < N;
    const bool v1 = (bn + lr + 64) < N;
    const uint32_t doff  = (uint32_t)((lr * SMPAD + lc) * 2);
    const uint32_t doff2 = (uint32_t)(((lr + 64) * SMPAD + lc) * 2);

    auto issue = [&](int w, int s) {
        const uint32_t st = sb + (uint32_t)s * STAGE_B;
        const int khi = w * GBK;
        const int klo = Kb + w * GBK;
        const bf16* Ap = A + (size_t)(bm + lr) * rowlen;
        const bf16* Bp = B + (size_t)(bn + lr) * rowlen;
        cp16(st + doff,               Ap + khi + lc,                        true);
        cp16(st + doff2,              Ap + (size_t)64 * rowlen + khi + lc,  true);
        cp16(st + TILE_B + doff,      Ap + klo + lc,                        true);
        cp16(st + TILE_B + doff2,     Ap + (size_t)64 * rowlen + klo + lc,  true);
        cp16(st + 2 * TILE_B + doff,  Bp + khi + lc,                        v0);
        cp16(st + 2 * TILE_B + doff2, Bp + (size_t)64 * rowlen + khi + lc,  v1);
        cp16(st + 3 * TILE_B + doff,  Bp + klo + lc,                        v0);
        cp16(st + 3 * TILE_B + doff2, Bp + (size_t)64 * rowlen + klo + lc,  v1);
    };

    const int a_row  = wm + (lane & 15);
    const int a_col  = (lane >> 4) * 8;
    const int b_row  = wn + (lane & 7);
    const int b_col4 = (lane >> 4) * 16 + ((lane >> 3) & 1) * 8;

    auto computeW = [&](uint32_t st) {
        uint32_t bqh[4][4], bql[4][4];
#pragma unroll
        for (int nt = 0; nt < 4; nt++) {
            const uint32_t bo = (uint32_t)(((b_row + nt * 8) * SMPAD + b_col4) * 2);
            ldsm_x4(bqh[nt][0], bqh[nt][1], bqh[nt][2], bqh[nt][3],
                    st + 2 * TILE_B + bo);
            ldsm_x4(bql[nt][0], bql[nt][1], bql[nt][2], bql[nt][3],
                    st + 3 * TILE_B + bo);
        }
#pragma unroll
        for (int ks = 0; ks < 2; ks++) {
            uint32_t af[4][4];
#pragma unroll
            for (int mt = 0; mt < 4; mt++) {
                const uint32_t ao =
                    (uint32_t)(((a_row + mt * 16) * SMPAD + ks * 16 + a_col) * 2);
                ldsm_x4(af[mt][0], af[mt][1], af[mt][2], af[mt][3], st + ao);  // Ahi
            }
#pragma unroll
            for (int mt = 0; mt < 4; mt++)
#pragma unroll
                for (int nt = 0; nt < 4; nt++)
                    mma16816(acc[mt][nt], af[mt], &bqh[nt][ks * 2]);   // hi*hi
#pragma unroll
            for (int mt = 0; mt < 4; mt++)
#pragma unroll
                for (int nt = 0; nt < 4; nt++)
                    mma16816(acc[mt][nt], af[mt], &bql[nt][ks * 2]);   // hi*lo
#pragma unroll
            for (int mt = 0; mt < 4; mt++) {
                const uint32_t ao =
                    (uint32_t)(((a_row + mt * 16) * SMPAD + ks * 16 + a_col) * 2);
                ldsm_x4(af[mt][0], af[mt][1], af[mt][2], af[mt][3],
                        st + TILE_B + ao);                              // Alo
            }
#pragma unroll
            for (int mt = 0; mt < 4; mt++)
#pragma unroll
                for (int nt = 0; nt < 4; nt++)
                    mma16816(acc[mt][nt], af[mt], &bqh[nt][ks * 2]);   // lo*hi
        }
    };

    issue(0, 0);
    cp_commit();
    for (int w = 0; w < per_seg; w++) {
        cp_wait0();
        __syncthreads();
        if (w + 1 < per_seg) { issue(w + 1, (w + 1) & 1); cp_commit(); }
        computeW(sb + (uint32_t)(w & 1) * STAGE_B);
    }

#pragma unroll
    for (int mt = 0; mt < 4; mt++) {
        const int row = bm + wm + mt * 16 + gid;
#pragma unroll
        for (int nt = 0; nt < 4; nt++) {
            const int col = bn + wn + nt * 8 + tig * 2;
            if (col < N) {
                *(float2*)&C[(size_t)row * N + col] =
                    make_float2(acc[mt][nt][0], acc[mt][nt][1]);
                *(float2*)&C[(size_t)(row + 8) * N + col] =
                    make_float2(acc[mt][nt][2], acc[mt][nt][3]);
            }
        }
    }
}

// ---------------------------------------------------------------------------
// Fused flash attention — Q & P resident, K/V streamed via cp.async
// co-resident hi/lo windows (R15 proven, byte-identical).
// ---------------------------------------------------------------------------
#define QS_LDA  392
#define BUFB    (128 * SMPAD * 2)        // 10240 per tile
#define KV_STAGE (2 * BUFB)              // hi+lo tiles per stage
#define FL_QS   0
#define FL_BS   100352
#define FL_PS   141312
#define FL_WMAX 208896
#define FL_WSUM 210944
#define FL_RM   212992
#define FL_RL   213504
#define FL_RC   214016
#define FL_SMEM 214528
#define PS_LDA  264

__global__ __launch_bounds__(256)
void flash_attn()
{
    extern __shared__ char sm[];
    const uint32_t sb = smem_u32(sm);
    float* wmax  = (float*)(sm + FL_WMAX);
    float* wsum  = (float*)(sm + FL_WSUM);
    float* row_m = (float*)(sm + FL_RM);
    float* row_l = (float*)(sm + FL_RL);
    float* row_c = (float*)(sm + FL_RC);
    bf16*  Ps    = (bf16*)(sm + FL_PS);

    const int h    = blockIdx.y;
    const int tid  = threadIdx.x;
    const int lane = tid & 31;
    const int wid  = tid >> 5;
    const int wm   = (wid >> 2) * 64;
    const int wn   = (wid & 3) * 32;
    const int gid  = lane >> 2;
    const int tig  = lane & 3;
    const int lr   = tid >> 2;
    const int lc   = (tid & 3) * 8;
    const int wq   = wid & 3;

    const bf16* Qh = g_Q2 + (size_t)h * S_LEN * (2 * Q_HEAD);
    const bf16* Kh = g_K2 + (size_t)h * S_LEN * (2 * Q_HEAD);
    const bf16* Vh = g_Vt2 + (size_t)h * V_DIM * (2 * S_LEN);

    const int a_row  = wm + (lane & 15);
    const int a_col  = (lane >> 4) * 8;
    const int b_row  = wn + (lane & 7);
    const int b_col4 = (lane >> 4) * 16 + ((lane >> 3) & 1) * 8;

    const uint32_t doff  = (uint32_t)((lr * SMPAD + lc) * 2);
    const uint32_t doff2 = (uint32_t)(((lr + 64) * SMPAD + lc) * 2);

    for (int half = 0; half < 2; half++) {
        const int qb = half ? (15 - (int)blockIdx.x) : (int)blockIdx.x;
        const int q0 = qb * 128;

        if (tid < 128) { row_m[tid] = -1e30f; row_l[tid] = 0.f; }
        // load Q tile (128 x 384 halves, hi|lo) once
        for (int idx = tid; idx < 128 * 48; idx += 256) {
            const int r = idx / 48, c = idx % 48;
            uint4 v = *(const uint4*)(Qh + (size_t)(q0 + r) * 384 + c * 8);
            *(uint4*)(sm + FL_QS + (uint32_t)((r * QS_LDA + c * 8) * 2)) = v;
        }
        float acc_o[4][4][4];
#pragma unroll
        for (int a = 0; a < 4; a++)
#pragma unroll
            for (int b = 0; b < 4; b++)
#pragma unroll
                for (int c = 0; c < 4; c++) acc_o[a][b][c] = 0.f;
        __syncthreads();

        for (int jb = 0; jb <= qb; jb++) {
            // ============== S = Q K^T : 6 windows, Q resident ==============
            float acc_s[4][4][4];
#pragma unroll
            for (int a = 0; a < 4; a++)
#pragma unroll
                for (int b = 0; b < 4; b++)
#pragma unroll
                    for (int c = 0; c < 4; c++) acc_s[a][b][c] = 0.f;

            auto issueK = [&](int w, int s) {
                const uint32_t st = sb + FL_BS + (uint32_t)s * KV_STAGE;
                const bf16* Kp = Kh + (size_t)(jb * 128 + lr) * 384 + lc;
                const bf16* Kp2 = Kp + (size_t)64 * 384;
                cp16(st + doff,         Kp  + w * 32,          true);
                cp16(st + doff2,        Kp2 + w * 32,          true);
                cp16(st + BUFB + doff,  Kp  + Q_HEAD + w * 32, true);
                cp16(st + BUFB + doff2, Kp2 + Q_HEAD + w * 32, true);
            };
            auto computeSW = [&](int w, uint32_t st) {
                uint32_t bqh[4][4], bql[4][4];
#pragma unroll
                for (int nt = 0; nt < 4; nt++) {
                    const uint32_t bo =
                        (uint32_t)(((b_row + nt * 8) * SMPAD + b_col4) * 2);
                    ldsm_x4(bqh[nt][0], bqh[nt][1], bqh[nt][2], bqh[nt][3], st + bo);
                    ldsm_x4(bql[nt][0], bql[nt][1], bql[nt][2], bql[nt][3],
                            st + BUFB + bo);
                }
#pragma unroll
                for (int ks = 0; ks < 2; ks++) {
                    uint32_t af[4][4];
#pragma unroll
                    for (int mt = 0; mt < 4; mt++) {
                        const uint32_t ao = (uint32_t)(((a_row + mt * 16) * QS_LDA +
                                             w * 32 + ks * 16 + a_col) * 2);
                        ldsm_x4(af[mt][0], af[mt][1], af[mt][2], af[mt][3],
                                sb + FL_QS + ao);                        // Qhi
                    }
#pragma unroll
                    for (int mt = 0; mt < 4; mt++)
#pragma unroll
                        for (int nt = 0; nt < 4; nt++)
                            mma16816(acc_s[mt][nt], af[mt], &bqh[nt][ks * 2]);
#pragma unroll
                    for (int mt = 0; mt < 4; mt++)
#pragma unroll
                        for (int nt = 0; nt < 4; nt++)
                            mma16816(acc_s[mt][nt], af[mt], &bql[nt][ks * 2]);
#pragma unroll
                    for (int mt = 0; mt < 4; mt++) {
                        const uint32_t ao = (uint32_t)(((a_row + mt * 16) * QS_LDA +
                                             Q_HEAD + w * 32 + ks * 16 + a_col) * 2);
                        ldsm_x4(af[mt][0], af[mt][1], af[mt][2], af[mt][3],
                                sb + FL_QS + ao);                        // Qlo
                    }
#pragma unroll
                    for (int mt = 0; mt < 4; mt++)
#pragma unroll
                        for (int nt = 0; nt < 4; nt++)
                            mma16816(acc_s[mt][nt], af[mt], &bqh[nt][ks * 2]);
                }
            };

            issueK(0, 0);
            cp_commit();
            for (int w = 0; w < 6; w++) {
                cp_wait0();
                __syncthreads();
                if (w + 1 < 6) { issueK(w + 1, (w + 1) & 1); cp_commit(); }
                computeSW(w, sb + FL_BS + (uint32_t)(w & 1) * KV_STAGE);
            }

            // ================= mask (diagonal block) ========================
            if (jb == qb) {
#pragma unroll
                for (int mt = 0; mt < 4; mt++) {
                    const int m0 = wm + mt * 16 + gid;
#pragma unroll
                    for (int nt = 0; nt < 4; nt++) {
                        const int n0 = wn + nt * 8 + tig * 2;
                        if (n0     > m0    ) acc_s[mt][nt][0] = -1e30f;
                        if (n0 + 1 > m0    ) acc_s[mt][nt][1] = -1e30f;
                        if (n0     > m0 + 8) acc_s[mt][nt][2] = -1e30f;
                        if (n0 + 1 > m0 + 8) acc_s[mt][nt][3] = -1e30f;
                    }
                }
            }
            __syncthreads();

            // ================= row max ======================================
            float rmx[4][2];
#pragma unroll
            for (int mt = 0; mt < 4; mt++) {
                float m0 = -1e30f, m1 = -1e30f;
#pragma unroll
                for (int nt = 0; nt < 4; nt++) {
                    m0 = fmaxf(m0, fmaxf(acc_s[mt][nt][0], acc_s[mt][nt][1]));
                    m1 = fmaxf(m1, fmaxf(acc_s[mt][nt][2], acc_s[mt][nt][3]));
                }
                rmx[mt][0] = m0; rmx[mt][1] = m1;
            }
#pragma unroll
            for (int o = 1; o < 4; o <<= 1)
#pragma unroll
                for (int mt = 0; mt < 4; mt++) {
                    rmx[mt][0] = fmaxf(rmx[mt][0], __shfl_xor_sync(0xffffffffu, rmx[mt][0], o));
                    rmx[mt][1] = fmaxf(rmx[mt][1], __shfl_xor_sync(0xffffffffu, rmx[mt][1], o));
                }
            if (tig == 0) {
#pragma unroll
                for (int mt = 0; mt < 4; mt++) {
                    wmax[wq * 128 + wm + mt * 16 + gid]     = rmx[mt][0];
                    wmax[wq * 128 + wm + mt * 16 + gid + 8] = rmx[mt][1];
                }
            }
            __syncthreads();

            // ========== P = exp(S-new_m), write Ps (hi|lo), partial sums ====
            float psum[4][2];
#pragma unroll
            for (int mt = 0; mt < 4; mt++) {
#pragma unroll
                for (int rr = 0; rr < 2; rr++) {
                    const int r = wm + mt * 16 + gid + rr * 8;
                    float bmx = fmaxf(fmaxf(wmax[r], wmax[128 + r]),
                                      fmaxf(wmax[256 + r], wmax[384 + r]));
                    const float newm = fmaxf(row_m[r], bmx);
                    float s = 0.f;
#pragma unroll
                    for (int nt = 0; nt < 4; nt++) {
                        const int n0 = wn + nt * 8 + tig * 2;
                        float p0 = __expf(acc_s[mt][nt][rr * 2 + 0] - newm);
                        float p1 = __expf(acc_s[mt][nt][rr * 2 + 1] - newm);
                        s += p0 + p1;
                        bf16 h0, l0, h1, l1;
                        split2(p0, h0, l0); split2(p1, h1, l1);
                        __nv_bfloat162 hp, lp;
                        hp.x = h0; hp.y = h1; lp.x = l0; lp.y = l1;
                        *(__nv_bfloat162*)&Ps[r * PS_LDA + n0]       = hp;
                        *(__nv_bfloat162*)&Ps[r * PS_LDA + 128 + n0] = lp;
                    }
                    psum[mt][rr] = s;
                }
            }
#pragma unroll
            for (int o = 1; o < 4; o <<= 1)
#pragma unroll
                for (int mt = 0; mt < 4; mt++) {
                    psum[mt][0] += __shfl_xor_sync(0xffffffffu, psum[mt][0], o);
                    psum[mt][1] += __shfl_xor_sync(0xffffffffu, psum[mt][1], o);
                }
            if (tig == 0) {
#pragma unroll
                for (int mt = 0; mt < 4; mt++) {
                    wsum[wq * 128 + wm + mt * 16 + gid]     = psum[mt][0];
                    wsum[wq * 128 + wm + mt * 16 + gid + 8] = psum[mt][1];
                }
            }
            __syncthreads();

            // ================= per-row state update ========================
            if (tid < 128) {
                const int r = tid;
                float bmx = fmaxf(fmaxf(wmax[r], wmax[128 + r]),
                                  fmaxf(wmax[256 + r], wmax[384 + r]));
                const float old  = row_m[r];
                const float newm = fmaxf(old, bmx);
                const float corr = __expf(old - newm);
                const float bs = wsum[r] + wsum[128 + r] + wsum[256 + r] + wsum[384 + r];
                row_l[r] = row_l[r] * corr + bs;
                row_m[r] = newm;
                row_c[r] = corr;
            }
            __syncthreads();

#pragma unroll
            for (int mt = 0; mt < 4; mt++) {
                const float c0 = row_c[wm + mt * 16 + gid];
                const float c1 = row_c[wm + mt * 16 + gid + 8];
#pragma unroll
                for (int nt = 0; nt < 4; nt++) {
                    acc_o[mt][nt][0] *= c0; acc_o[mt][nt][1] *= c0;
                    acc_o[mt][nt][2] *= c1; acc_o[mt][nt][3] *= c1;
                }
            }

            // ============== O += P V : 4 windows, P resident ===============
            auto issueV = [&](int w, int s) {
                const uint32_t st = sb + FL_BS + (uint32_t)s * KV_STAGE;
                const bf16* Vp = Vh + (size_t)lr * (2 * S_LEN) + jb * 128 + lc;
                const bf16* Vp2 = Vp + (size_t)64 * (2 * S_LEN);
                cp16(st + doff,         Vp  + w * 32,         true);
                cp16(st + doff2,        Vp2 + w * 32,         true);
                cp16(st + BUFB + doff,  Vp  + S_LEN + w * 32, true);
                cp16(st + BUFB + doff2, Vp2 + S_LEN + w * 32, true);
            };
            auto computePVW = [&](int w, uint32_t st) {
                uint32_t bqh[4][4], bql[4][4];
#pragma unroll
                for (int nt = 0; nt < 4; nt++) {
                    const uint32_t bo =
                        (uint32_t)(((b_row + nt * 8) * SMPAD + b_col4) * 2);
                    ldsm_x4(bqh[nt][0], bqh[nt][1], bqh[nt][2], bqh[nt][3], st + bo);
                    ldsm_x4(bql[nt][0], bql[nt][1], bql[nt][2], bql[nt][3],
                            st + BUFB + bo);
                }
#pragma unroll
                for (int ks = 0; ks < 2; ks++) {
                    uint32_t af[4][4];
#pragma unroll
                    for (int mt = 0; mt < 4; mt++) {
                        const uint32_t ao = (uint32_t)(((a_row + mt * 16) * PS_LDA +
                                             w * 32 + ks * 16 + a_col) * 2);
                        ldsm_x4(af[mt][0], af[mt][1], af[mt][2], af[mt][3],
                                sb + FL_PS + ao);                        // Phi
                    }
#pragma unroll
                    for (int mt = 0; mt < 4; mt++)
#pragma unroll
                        for (int nt = 0; nt < 4; nt++)
                            mma16816(acc_o[mt][nt], af[mt], &bqh[nt][ks * 2]);
#pragma unroll
                    for (int mt = 0; mt < 4; mt++)
#pragma unroll
                        for (int nt = 0; nt < 4; nt++)
                            mma16816(acc_o[mt][nt], af[mt], &bql[nt][ks * 2]);
#pragma unroll
                    for (int mt = 0; mt < 4; mt++) {
                        const uint32_t ao = (uint32_t)(((a_row + mt * 16) * PS_LDA +
                                             128 + w * 32 + ks * 16 + a_col) * 2);
                        ldsm_x4(af[mt][0], af[mt][1], af[mt][2], af[mt][3],
                                sb + FL_PS + ao);                        // Plo
                    }
#pragma unroll
                    for (int mt = 0; mt < 4; mt++)
#pragma unroll
                        for (int nt = 0; nt < 4; nt++)
                            mma16816(acc_o[mt][nt], af[mt], &bqh[nt][ks * 2]);
                }
            };

            issueV(0, 0);
            cp_commit();
            for (int w = 0; w < 4; w++) {
                cp_wait0();
                __syncthreads();
                if (w + 1 < 4) { issueV(w + 1, (w + 1) & 1); cp_commit(); }
                computePVW(w, sb + FL_BS + (uint32_t)(w & 1) * KV_STAGE);
            }
            __syncthreads();   // protect Ps/KV stage reuse next jb
        }

        // ================= epilogue: O / l -> attn2 (split-2) ===============
#pragma unroll
        for (int mt = 0; mt < 4; mt++) {
            const int r0 = wm + mt * 16 + gid;
            const int r1 = r0 + 8;
            const float inv0 = 1.f / row_l[r0];
            const float inv1 = 1.f / row_l[r1];
            bf16* d0 = g_attn2 + (size_t)(q0 + r0) * (2 * NH * V_DIM);
            bf16* d1 = g_attn2 + (size_t)(q0 + r1) * (2 * NH * V_DIM);
#pragma unroll
            for (int nt = 0; nt < 4; nt++) {
                const int c = h * V_DIM + wn + nt * 8 + tig * 2;
                bf16 h0, l0, h1, l1;
                split2(acc_o[mt][nt][0] * inv0, h0, l0);
                split2(acc_o[mt][nt][1] * inv0, h1, l1);
                __nv_bfloat162 hp, lp;
                hp.x = h0; hp.y = h1; lp.x = l0; lp.y = l1;
                *(__nv_bfloat162*)&d0[c]              = hp;
                *(__nv_bfloat162*)&d0[NH * V_DIM + c] = lp;
                split2(acc_o[mt][nt][2] * inv1, h0, l0);
                split2(acc_o[mt][nt][3] * inv1, h1, l1);
                hp.x = h0; hp.y = h1; lp.x = l0; lp.y = l1;
                *(__nv_bfloat162*)&d1[c]              = hp;
                *(__nv_bfloat162*)&d1[NH * V_DIM + c] = lp;
            }
        }
        __syncthreads();
    }
}

// ---------------------------------------------------------------------------
// One merged split-2 kernel for all 6 input/weight splits.
// 8 floats per thread iteration -> one 16B hi store + one 16B lo store.
// ---------------------------------------------------------------------------
struct SplitArgs {
    const float* x0; bf16* y0;
    const float* x1; bf16* y1;
    const float* x2; bf16* y2;
    const float* x3; bf16* y3;
    const float* x4; bf16* y4;
    const float* x5; bf16* y5;
};

__global__ __launch_bounds__(256)
void split2_all(SplitArgs args)
{
    int b = blockIdx.x;
    const float* x; bf16* y; int C, row;
    if      (b < 2048)  { x = args.x0; y = args.y0; C = 4096; row = b; }
    else if (b < 3584)  { x = args.x1; y = args.y1; C = 4096; row = b - 2048; }
    else if (b < 4160)  { x = args.x2; y = args.y2; C = 4096; row = b - 3584; }
    else if (b < 7232)  { x = args.x3; y = args.y3; C = 1536; row = b - 4160; }
    else if (b < 11328) { x = args.x4; y = args.y4; C = 512;  row = b - 7232; }
    else                { x = args.x5; y = args.y5; C = 2048; row = b - 11328; }

    const float* xr = x + (size_t)row * C;
    bf16* yr = y + (size_t)row * 2 * C;
    for (int j = threadIdx.x * 8; j < C; j += 256 * 8) {
        float4 v0 = *(const float4*)&xr[j];
        float4 v1 = *(const float4*)&xr[j + 4];
        bf16 hv[8], lv[8];
        split2(v0.x, hv[0], lv[0]); split2(v0.y, hv[1], lv[1]);
        split2(v0.z, hv[2], lv[2]); split2(v0.w, hv[3], lv[3]);
        split2(v1.x, hv[4], lv[4]); split2(v1.y, hv[5], lv[5]);
        split2(v1.z, hv[6], lv[6]); split2(v1.w, hv[7], lv[7]);
        *(uint4*)&yr[j]     = *(const uint4*)hv;
        *(uint4*)&yr[C + j] = *(const uint4*)lv;
    }
}

// ---------------------------------------------------------------------------
// Merged RMSNorm (q rows then kv rows) fused with split-2 output
// ---------------------------------------------------------------------------
__global__ __launch_bounds__(256)
void rmsnorm_split_all(const float* __restrict__ qkv,
                       const float* __restrict__ qw,
                       const float* __restrict__ kw,
                       bf16* __restrict__ yq, bf16* __restrict__ yk)
{
    const int b = blockIdx.x;
    const float* xr; const float* w; bf16* yr; int len;
    if (b < S_LEN) {
        xr = qkv + (size_t)b * QKV_W;           w = qw;
        yr = yq + (size_t)b * 2 * Q_LORA;       len = Q_LORA;
    } else {
        const int r = b - S_LEN;
        xr = qkv + (size_t)r * QKV_W + Q_LORA;  w = kw;
        yr = yk + (size_t)r * 2 * KV_LORA;      len = KV_LORA;
    }

    float ss = 0.f;
    for (int j = threadIdx.x; j < len; j += 256) { float v = xr[j]; ss += v * v; }
    __shared__ float red[256];
    red[threadIdx.x] = ss;
    __syncthreads();
    for (int s = 128; s > 0; s >>= 1) {
        if (threadIdx.x < s) red[threadIdx.x] += red[threadIdx.x + s];
        __syncthreads();
    }
    const float inv = rsqrtf(red[0] / (float)len + RMS_EPS);
    for (int j = threadIdx.x; j < len; j += 256) {
        bf16 h, l;
        split2(w[j] * xr[j] * inv, h, l);
        yr[j] = h; yr[len + j] = l;
    }
}

// ---------------------------------------------------------------------------
// RoPE + merged Q/K assemble, V transpose (R15 proven)
// ---------------------------------------------------------------------------
__device__ __forceinline__ void rope_cs(int pos, int jj, float& c, float& s)
{
    int i = jj & 31;
    float inv = __expf(-((float)(2 * i) / (float)QK_ROPE) * logf(ROPE_BASE));
    float ang = (float)pos * inv;
    c = cosf(ang);
    s = sinf(ang);
}

__global__ void assemble_qk(float scale)
{
    const int s = blockIdx.x, h = blockIdx.y;
    const int t = threadIdx.x;
    if (t < Q_HEAD) {
        const int j = t;
        const float* src = g_qfull + (size_t)s * QB_OUT + h * Q_HEAD;
        float v = src[j];
        if (j >= QK_NOPE) {
            int jj = j - QK_NOPE;
            float c, sn;
            rope_cs(s, jj, c, sn);
            float other = (jj < 32) ? -src[QK_NOPE + jj + 32] : src[QK_NOPE + jj - 32];
            v = v * c + other * sn;
        }
        v *= scale;
        bf16 hh, ll;
        split2(v, hh, ll);
        bf16* dst = g_Q2 + ((size_t)h * S_LEN + s) * 2 * Q_HEAD;
        dst[j] = hh; dst[Q_HEAD + j] = ll;
    } else {
        const int j = t - Q_HEAD;
        float v;
        if (j < QK_NOPE) {
            v = g_kvexp[(size_t)s * KVB_OUT + h * (QK_NOPE + V_DIM) + j];
        } else {
            int jj = j - QK_NOPE;
            const float* pe = g_qkv_raw + (size_t)s * QKV_W + Q_LORA + KV_LORA;
            float c, sn;
            rope_cs(s, jj, c, sn);
            float other = (jj < 32) ? -pe[jj + 32] : pe[jj - 32];
            v = pe[jj] * c + other * sn;
        }
        bf16 hh, ll;
        split2(v, hh, ll);
        bf16* dst = g_K2 + ((size_t)h * S_LEN + s) * 2 * Q_HEAD;
        dst[j] = hh; dst[Q_HEAD + j] = ll;
    }
}

__global__ void assemble_vt()
{
    __shared__ float sm[32][33];
    const int h = blockIdx.z;
    const int s0 = blockIdx.x * 32, d0 = blockIdx.y * 32;
    const int tx = threadIdx.x, ty = threadIdx.y;
    sm[ty][tx] = g_kvexp[(size_t)(s0 + ty) * KVB_OUT +
                         h * (QK_NOPE + V_DIM) + QK_NOPE + d0 + tx];
    __syncthreads();
    const int d = d0 + ty, s = s0 + tx;
    bf16 hh, ll;
    split2(sm[tx][ty], hh, ll);
    bf16* dst = g_Vt2 + ((size_t)h * V_DIM + d) * 2 * S_LEN;
    dst[s] = hh; dst[S_LEN + s] = ll;
}

// ---------------------------------------------------------------------------
// Host launch
// ---------------------------------------------------------------------------
extern "C" void kernel_launch(void* const* d_in, const int* in_sizes, int n_in,
                              void* d_out, int out_size)
{
    (void)in_sizes; (void)n_in; (void)out_size;
    const float* hidden = (const float*)d_in[0];
    const float* wq_a   = (const float*)d_in[2];
    const float* qnw    = (const float*)d_in[3];
    const float* wq_b   = (const float*)d_in[4];
    const float* wkv_a  = (const float*)d_in[5];
    const float* kvnw   = (const float*)d_in[6];
    const float* wkv_b  = (const float*)d_in[7];
    const float* wo     = (const float*)d_in[8];
    float* out = (float*)d_out;

    float *qkv_raw, *qfull, *kvexp;
    bf16 *hidden2, *wqkva2, *qlat2, *wqb2, *ckv2, *wkvb2, *attn2, *wo2;
    cudaGetSymbolAddress((void**)&qkv_raw, g_qkv_raw);
    cudaGetSymbolAddress((void**)&qfull,   g_qfull);
    cudaGetSymbolAddress((void**)&kvexp,   g_kvexp);
    cudaGetSymbolAddress((void**)&hidden2, g_hidden2);
    cudaGetSymbolAddress((void**)&wqkva2,  g_wqkva2);
    cudaGetSymbolAddress((void**)&qlat2,   g_qlat2);
    cudaGetSymbolAddress((void**)&wqb2,    g_wqb2);
    cudaGetSymbolAddress((void**)&ckv2,    g_ckv2);
    cudaGetSymbolAddress((void**)&wkvb2,   g_wkvb2);
    cudaGetSymbolAddress((void**)&attn2,   g_attn2);
    cudaGetSymbolAddress((void**)&wo2,     g_wo2);

    const float softmax_scale = rsqrtf((float)Q_HEAD);
    dim3 blk(256);

    cudaFuncSetAttribute(flash_attn, cudaFuncAttributeMaxDynamicSharedMemorySize,
                         FL_SMEM);
    cudaFuncSetAttribute(gemm_bf16_tn, cudaFuncAttributeMaxDynamicSharedMemorySize,
                         GEMM_SMEM);

    SplitArgs sa;
    sa.x0 = hidden; sa.y0 = hidden2;
    sa.x1 = wq_a;   sa.y1 = wqkva2;
    sa.x2 = wkv_a;  sa.y2 = wqkva2 + (size_t)Q_LORA * 2 * HID;
    sa.x3 = wq_b;   sa.y3 = wqb2;
    sa.x4 = wkv_b;  sa.y4 = wkvb2;
    sa.x5 = wo;     sa.y5 = wo2;
    split2_all<<<15424, 256>>>(sa);

    // 1+2 fused: [q_lat_raw | kv] = hidden @ [wq_a | wkv_a]^T
    gemm_bf16_tn<<<dim3((QKV_W + 127) / 128, S_LEN / 128, 1), blk, GEMM_SMEM>>>(
        hidden2, wqkva2, qkv_raw, S_LEN, QKV_W, HID);
    // merged RMSNorms
    rmsnorm_split_all<<<2 * S_LEN, 256>>>(qkv_raw, qnw, kvnw, qlat2, ckv2);
    // q = q_lat @ wq_b^T
    gemm_bf16_tn<<<dim3(QB_OUT / 128, S_LEN / 128, 1), blk, GEMM_SMEM>>>(
        qlat2, wqb2, qfull, S_LEN, QB_OUT, Q_LORA);
    // kv_exp = ckv @ wkv_b^T
    gemm_bf16_tn<<<dim3(KVB_OUT / 128, S_LEN / 128, 1), blk, GEMM_SMEM>>>(
        ckv2, wkvb2, kvexp, S_LEN, KVB_OUT, KV_LORA);

    // assemble attention operands
    assemble_qk<<<dim3(S_LEN, NH), 2 * Q_HEAD>>>(softmax_scale);
    assemble_vt<<<dim3(S_LEN / 32, V_DIM / 32, NH), dim3(32, 32)>>>();

    // fused flash attention (Q/P resident, cp.async K/V windows)
    flash_attn<<<dim3(8, NH), blk, FL_SMEM>>>();

    // output projection
    gemm_bf16_tn<<<dim3(HID / 128, S_LEN / 128, 1), blk, GEMM_SMEM>>>(
        attn2, wo2, out, S_LEN, HID, NH * V_DIM);
}